// round 1
// baseline (speedup 1.0000x reference)
#include <cuda_runtime.h>
#include <cstdint>

#define T_CAP 64
#define BATCH 256
#define DEC   1024
#define HID   1024
#define ATTN  128

// ---------------- scratch (static device memory; no allocations) ----------------
__device__ float g_Uv[BATCH * T_CAP * ATTN];   // 8 MB  : U(feats)+b_attn, [b][t][a]
__device__ float g_h[2][BATCH * HID];          // double-buffered hidden state
__device__ float g_c[BATCH * HID];             // cell state (uniquely owned per (b,n))
__device__ float g_Wh[BATCH * ATTN];           // h @ W_attn^T per step
__device__ float g_ctx[BATCH * DEC];           // attention context per step

// ---------------- helpers ----------------
__device__ __forceinline__ uint32_t f2tf(float f) {
    uint32_t u;
    asm("cvt.rna.tf32.f32 %0, %1;" : "=r"(u) : "f"(f));
    return u;
}

__device__ __forceinline__ void mma8(float* c, const uint32_t* a, const uint32_t* b) {
    asm volatile(
        "mma.sync.aligned.m16n8k8.row.col.f32.tf32.tf32.f32 "
        "{%0,%1,%2,%3}, {%4,%5,%6,%7}, {%8,%9}, {%0,%1,%2,%3};\n"
        : "+f"(c[0]), "+f"(c[1]), "+f"(c[2]), "+f"(c[3])
        : "r"(a[0]), "r"(a[1]), "r"(a[2]), "r"(a[3]),
          "r"(b[0]), "r"(b[1]));
}

__device__ __forceinline__ void cp16(float* s, const float* g) {
    uint32_t sa = (uint32_t)__cvta_generic_to_shared(s);
    asm volatile("cp.async.ca.shared.global [%0], [%1], 16;\n" :: "r"(sa), "l"(g));
}
#define CP_COMMIT() asm volatile("cp.async.commit_group;\n" ::)
#define CP_WAIT1()  asm volatile("cp.async.wait_group 1;\n" ::)
#define CP_WAIT0()  asm volatile("cp.async.wait_group 0;\n" ::)

__device__ __forceinline__ float sigf(float x) { return 1.0f / (1.0f + __expf(-x)); }

// ---------------- init: zero h0, c ----------------
__global__ void init_kernel() {
    int i = blockIdx.x * blockDim.x + threadIdx.x;
    if (i < BATCH * HID) {
        g_h[0][i] = 0.0f;
        g_c[i]    = 0.0f;
    }
}

// ---------------- Uv = feats @ U_attn^T + b_attn  (tf32 mma) ----------------
// M = B*T_CAP = 16384 (r = b*64 + t), N = ATTN = 128, K = 1024
// grid (128, 2), 256 threads. BM=128, BN=64, BK=16.
__global__ __launch_bounds__(256) void uv_kernel(
    const float* __restrict__ dh, const float* __restrict__ U_attn,
    const float* __restrict__ b_attn)
{
    __shared__ __align__(16) float As[2][128][20];
    __shared__ __align__(16) float Bs[2][64][20];

    const int tid = threadIdx.x;
    const int m0 = blockIdx.x * 128;
    const int n0 = blockIdx.y * 64;

    const int am = tid >> 1;
    const int ak = (tid & 1) * 8;
    const int bj = tid >> 2;
    const int bk = (tid & 3) * 4;

    const int r = m0 + am;
    const long abase = ((long)((r & 63) * 256 + (r >> 6))) * 1024;  // feats row base
    const long bbase = (long)(n0 + bj) * 1024;

    const int warp = tid >> 5, lane = tid & 31;
    const int wm = (warp >> 2) * 64;
    const int wn = (warp & 3) * 16;
    const int lr = lane >> 2;
    const int lc = lane & 3;

    float acc[4][2][4];
#pragma unroll
    for (int i = 0; i < 4; i++)
#pragma unroll
        for (int j = 0; j < 2; j++)
#pragma unroll
            for (int k = 0; k < 4; k++) acc[i][j][k] = 0.0f;

    const int NS = 1024 / 16;

    // stage 0
    {
        cp16(&As[0][am][ak],     dh + abase + 0 + ak);
        cp16(&As[0][am][ak + 4], dh + abase + 0 + ak + 4);
        cp16(&Bs[0][bj][bk],     U_attn + bbase + 0 + bk);
        CP_COMMIT();
    }

    for (int s = 0; s < NS; s++) {
        if (s + 1 < NS) {
            int buf = (s + 1) & 1, k0 = (s + 1) * 16;
            cp16(&As[buf][am][ak],     dh + abase + k0 + ak);
            cp16(&As[buf][am][ak + 4], dh + abase + k0 + ak + 4);
            cp16(&Bs[buf][bj][bk],     U_attn + bbase + k0 + bk);
            CP_COMMIT();
            CP_WAIT1();
        } else {
            CP_WAIT0();
        }
        __syncthreads();
        const int buf = s & 1;
#pragma unroll
        for (int kk = 0; kk < 16; kk += 8) {
            uint32_t af[4][4], bf[2][2];
#pragma unroll
            for (int fm = 0; fm < 4; fm++) {
                int rr = wm + fm * 16 + lr;
                af[fm][0] = f2tf(As[buf][rr][kk + lc]);
                af[fm][1] = f2tf(As[buf][rr + 8][kk + lc]);
                af[fm][2] = f2tf(As[buf][rr][kk + lc + 4]);
                af[fm][3] = f2tf(As[buf][rr + 8][kk + lc + 4]);
            }
#pragma unroll
            for (int fn = 0; fn < 2; fn++) {
                int jc = wn + fn * 8 + lr;
                bf[fn][0] = f2tf(Bs[buf][jc][kk + lc]);
                bf[fn][1] = f2tf(Bs[buf][jc][kk + lc + 4]);
            }
#pragma unroll
            for (int fm = 0; fm < 4; fm++)
#pragma unroll
                for (int fn = 0; fn < 2; fn++) mma8(acc[fm][fn], af[fm], bf[fn]);
        }
        __syncthreads();
    }

    // epilogue: + b_attn, store to g_Uv
#pragma unroll
    for (int fm = 0; fm < 4; fm++) {
#pragma unroll
        for (int fn = 0; fn < 2; fn++) {
            int rr = m0 + wm + fm * 16 + lr;
            int a  = n0 + wn + fn * 8 + 2 * lc;
            float ba0 = b_attn[a], ba1 = b_attn[a + 1];
            float2 v0 = make_float2(acc[fm][fn][0] + ba0, acc[fm][fn][1] + ba1);
            float2 v1 = make_float2(acc[fm][fn][2] + ba0, acc[fm][fn][3] + ba1);
            *(float2*)&g_Uv[rr * ATTN + a]       = v0;
            *(float2*)&g_Uv[(rr + 8) * ATTN + a] = v1;
        }
    }
}

// ---------------- Wh = h @ W_attn^T (SIMT; 256x128x1024, tiny) ----------------
// grid (8, 8): BM=32, BN=16
__global__ __launch_bounds__(256) void wh_kernel(const float* __restrict__ W_attn, int cur)
{
    __shared__ float hs[32][33];
    __shared__ float ws[16][33];
    const float* h = g_h[cur];
    const int tid = threadIdx.x;
    const int m0 = blockIdx.x * 32, a0 = blockIdx.y * 16;
    const int mi = tid >> 4, ai = tid & 15;
    float acc0 = 0.0f, acc1 = 0.0f;

    for (int k0 = 0; k0 < 1024; k0 += 32) {
        int hr = tid >> 3, hc = (tid & 7) * 4;
        float4 hv = *(const float4*)&h[(m0 + hr) * 1024 + k0 + hc];
        hs[hr][hc] = hv.x; hs[hr][hc + 1] = hv.y; hs[hr][hc + 2] = hv.z; hs[hr][hc + 3] = hv.w;
        int wr = tid >> 4, wc = (tid & 15) * 2;
        float2 wv = *(const float2*)&W_attn[(a0 + wr) * 1024 + k0 + wc];
        ws[wr][wc] = wv.x; ws[wr][wc + 1] = wv.y;
        __syncthreads();
#pragma unroll
        for (int kk = 0; kk < 32; kk++) {
            float w = ws[ai][kk];
            acc0 += hs[mi][kk] * w;
            acc1 += hs[mi + 16][kk] * w;
        }
        __syncthreads();
    }
    g_Wh[(m0 + mi) * ATTN + a0 + ai]      = acc0;
    g_Wh[(m0 + mi + 16) * ATTN + a0 + ai] = acc1;
}

// ---------------- attention: energies -> masked softmax -> context ----------------
// grid (256) blocks, one per batch row b; 256 threads
__global__ __launch_bounds__(256) void attn_kernel(
    const float* __restrict__ dh, const int* __restrict__ caps,
    const float* __restrict__ w_attn)
{
    const int b = blockIdx.x, tid = threadIdx.x;
    const int warp = tid >> 5, lane = tid & 31;
    __shared__ float wh_s[ATTN], wa_s[ATTN], e_s[T_CAP], p_s[T_CAP];

    if (tid < ATTN) {
        wh_s[tid] = g_Wh[b * ATTN + tid];
        wa_s[tid] = w_attn[tid];
    }
    __syncthreads();

    for (int t = warp; t < T_CAP; t += 8) {
        const float* uv = g_Uv + (b * T_CAP + t) * ATTN;
        float s = 0.0f;
#pragma unroll
        for (int a = lane; a < ATTN; a += 32)
            s += wa_s[a] * tanhf(wh_s[a] + uv[a]);
#pragma unroll
        for (int off = 16; off; off >>= 1) s += __shfl_xor_sync(0xffffffffu, s, off);
        if (lane == 0) {
            int cp = caps[t * BATCH + b];
            e_s[t] = (cp != 0 && cp != 2) ? s : -1e30f;
        }
    }
    __syncthreads();

    if (warp == 0) {
        float e0 = e_s[lane], e1 = e_s[lane + 32];
        float mx = fmaxf(e0, e1);
#pragma unroll
        for (int off = 16; off; off >>= 1) mx = fmaxf(mx, __shfl_xor_sync(0xffffffffu, mx, off));
        float x0 = __expf(e0 - mx), x1 = __expf(e1 - mx);
        float sm = x0 + x1;
#pragma unroll
        for (int off = 16; off; off >>= 1) sm += __shfl_xor_sync(0xffffffffu, sm, off);
        float inv = 1.0f / sm;
        p_s[lane]      = x0 * inv;
        p_s[lane + 32] = x1 * inv;
    }
    __syncthreads();

    // ctx[b, d] = sum_t p[t] * feats[b, t, d]; each thread owns 4 strided d's
    float a0 = 0.f, a1 = 0.f, a2 = 0.f, a3 = 0.f;
#pragma unroll 4
    for (int t = 0; t < T_CAP; t++) {
        float p = p_s[t];
        const float* f = dh + (long)(t * BATCH + b) * DEC + tid;
        a0 += p * f[0];
        a1 += p * f[256];
        a2 += p * f[512];
        a3 += p * f[768];
    }
    float* cx = g_ctx + b * DEC + tid;
    cx[0] = a0; cx[256] = a1; cx[512] = a2; cx[768] = a3;
}

// ---------------- gates GEMM (tf32 mma) + fused LSTM pointwise ----------------
// gates = [ctx|h_prev](256x2048) @ [W_ih|W_hh]^T with gate-interleaved columns:
// block covers m-tile 128 x 16 n-values x 4 gates (j = 4*nl + gate). grid (2, 64).
__global__ __launch_bounds__(256) void gates_kernel(
    const float* __restrict__ W_ih, const float* __restrict__ W_hh,
    const float* __restrict__ b_ih, const float* __restrict__ b_hh,
    float* __restrict__ out, int step, int T_feat)
{
    __shared__ __align__(16) float smem[128 * 68];  // overlay: As|Bs then gates tile
    float (*As)[128][20] = (float(*)[128][20])smem;            // 2*128*20 = 5120 floats
    float (*Bs)[64][20]  = (float(*)[64][20])(smem + 5120);    // 2*64*20  = 2560 floats
    __shared__ float bias_s[64];

    const int tid = threadIdx.x;
    const int m0 = blockIdx.x * 128;
    const int n0 = blockIdx.y * 16;
    const float* hprev = g_h[step & 1];
    float* hnext = g_h[(step + 1) & 1];

    if (tid < 64) {
        int row = (tid & 3) * 1024 + n0 + (tid >> 2);
        bias_s[tid] = b_ih[row] + b_hh[row];
    }

    const int am = tid >> 1;
    const int ak = (tid & 1) * 8;
    const int bj = tid >> 2;
    const int bk = (tid & 3) * 4;
    const long brow = (long)((bj & 3) * 1024 + n0 + (bj >> 2)) * 1024;
    const long arow = (long)(m0 + am) * 1024;

    const int warp = tid >> 5, lane = tid & 31;
    const int wm = (warp >> 2) * 64;
    const int wn = (warp & 3) * 16;
    const int lr = lane >> 2;
    const int lc = lane & 3;

    float acc[4][2][4];
#pragma unroll
    for (int i = 0; i < 4; i++)
#pragma unroll
        for (int j = 0; j < 2; j++)
#pragma unroll
            for (int k = 0; k < 4; k++) acc[i][j][k] = 0.0f;

    const int NS = 2048 / 16;

    // stage 0 (k0 = 0 < 1024: A from ctx, B from W_ih)
    {
        cp16(&As[0][am][ak],     g_ctx + arow + ak);
        cp16(&As[0][am][ak + 4], g_ctx + arow + ak + 4);
        cp16(&Bs[0][bj][bk],     W_ih + brow + bk);
        CP_COMMIT();
    }

    for (int s = 0; s < NS; s++) {
        if (s + 1 < NS) {
            int buf = (s + 1) & 1, k0 = (s + 1) * 16;
            const float* Asrc = (k0 < 1024) ? g_ctx : hprev;
            const float* Bsrc = (k0 < 1024) ? W_ih : W_hh;
            int kb = k0 & 1023;
            cp16(&As[buf][am][ak],     Asrc + arow + kb + ak);
            cp16(&As[buf][am][ak + 4], Asrc + arow + kb + ak + 4);
            cp16(&Bs[buf][bj][bk],     Bsrc + brow + kb + bk);
            CP_COMMIT();
            CP_WAIT1();
        } else {
            CP_WAIT0();
        }
        __syncthreads();
        const int buf = s & 1;
#pragma unroll
        for (int kk = 0; kk < 16; kk += 8) {
            uint32_t af[4][4], bf[2][2];
#pragma unroll
            for (int fm = 0; fm < 4; fm++) {
                int rr = wm + fm * 16 + lr;
                af[fm][0] = f2tf(As[buf][rr][kk + lc]);
                af[fm][1] = f2tf(As[buf][rr + 8][kk + lc]);
                af[fm][2] = f2tf(As[buf][rr][kk + lc + 4]);
                af[fm][3] = f2tf(As[buf][rr + 8][kk + lc + 4]);
            }
#pragma unroll
            for (int fn = 0; fn < 2; fn++) {
                int jc = wn + fn * 8 + lr;
                bf[fn][0] = f2tf(Bs[buf][jc][kk + lc]);
                bf[fn][1] = f2tf(Bs[buf][jc][kk + lc + 4]);
            }
#pragma unroll
            for (int fm = 0; fm < 4; fm++)
#pragma unroll
                for (int fn = 0; fn < 2; fn++) mma8(acc[fm][fn], af[fm], bf[fn]);
        }
        __syncthreads();
    }

    // dump accumulators to smem gates tile [128][64] (stride 68)
    float (*gs)[68] = (float(*)[68])smem;
#pragma unroll
    for (int fm = 0; fm < 4; fm++) {
#pragma unroll
        for (int fn = 0; fn < 2; fn++) {
            int m = wm + fm * 16 + lr;
            int j = wn + fn * 8 + 2 * lc;
            *(float2*)&gs[m][j]     = make_float2(acc[fm][fn][0], acc[fm][fn][1]);
            *(float2*)&gs[m + 8][j] = make_float2(acc[fm][fn][2], acc[fm][fn][3]);
        }
    }
    __syncthreads();

    // fused LSTM pointwise: read (i,f,g,o) quadruple per (m, n)
    for (int q = tid; q < 128 * 16; q += 256) {
        int ml = q & 127, nl = q >> 7;
        float4 g4 = *(float4*)&gs[ml][nl * 4];
        float iv = g4.x + bias_s[nl * 4 + 0];
        float fv = g4.y + bias_s[nl * 4 + 1];
        float gv = g4.z + bias_s[nl * 4 + 2];
        float ov = g4.w + bias_s[nl * 4 + 3];
        int b = m0 + ml, n = n0 + nl;
        int idx = b * HID + n;
        float cold = g_c[idx];
        float cn = sigf(fv) * cold + sigf(iv) * tanhf(gv);
        float hn = sigf(ov) * tanhf(cn);
        g_c[idx] = cn;
        hnext[idx] = hn;
        out[(long)(b * T_feat + step) * HID + n] = hn;
    }
}

// ---------------- launcher ----------------
extern "C" void kernel_launch(void* const* d_in, const int* in_sizes, int n_in,
                              void* d_out, int out_size)
{
    // input order per setup_inputs; target_feature_length scalar may or may not
    // appear as an input — detect via size-1 entry at index 2.
    int base = 2;
    if (n_in >= 11 && in_sizes[2] == 1) base = 3;

    const float* dh     = (const float*)d_in[0];
    const int*   caps   = (const int*)d_in[1];
    const float* W_attn = (const float*)d_in[base + 0];
    const float* U_attn = (const float*)d_in[base + 1];
    const float* b_attn = (const float*)d_in[base + 2];
    const float* w_attn = (const float*)d_in[base + 3];
    const float* W_ih   = (const float*)d_in[base + 4];
    const float* W_hh   = (const float*)d_in[base + 5];
    const float* b_ih   = (const float*)d_in[base + 6];
    const float* b_hh   = (const float*)d_in[base + 7];
    float* out = (float*)d_out;

    const int T_feat = out_size / (BATCH * HID);  // 28

    init_kernel<<<(BATCH * HID + 255) / 256, 256>>>();
    uv_kernel<<<dim3(128, 2), 256>>>(dh, U_attn, b_attn);

    for (int s = 0; s < T_feat; s++) {
        wh_kernel<<<dim3(8, 8), 256>>>(W_attn, s & 1);
        attn_kernel<<<BATCH, 256>>>(dh, caps, w_attn);
        gates_kernel<<<dim3(2, 64), 256>>>(W_ih, W_hh, b_ih, b_hh, out, s, T_feat);
    }
}